// round 1
// baseline (speedup 1.0000x reference)
#include <cuda_runtime.h>
#include <cstdint>

#define NN 50000
#define EE 400000
#define FF 256
#define HH 512
#define CC 3

// ---------------- device scratch (static globals: no runtime allocation) ----------------
__device__ float g_X[(size_t)NN * HH];   // current activations
__device__ float g_T[(size_t)NN * HH];   // aggregation output
__device__ float g_S[(size_t)NN * CC];   // final small-gemm output
__device__ float g_dinv[NN];
__device__ float g_coef[EE];
__device__ int   g_srcA[EE];
__device__ int   g_dstA[EE];
__device__ int   g_col[EE];
__device__ int   g_cnt[NN];
__device__ int   g_fill[NN];
__device__ int   g_rowptr[NN + 1];
__device__ unsigned g_is32;

// ---------------- preprocessing kernels ----------------
__global__ void zero_kernel() {
    int i = blockIdx.x * blockDim.x + threadIdx.x;
    if (i < NN) { g_cnt[i] = 0; g_fill[i] = 0; }
    if (i == 0) g_is32 = 0u;
}

// Detect edge_index dtype: view buffer as u32. If underlying data is int64
// (values in [0, 50000), nonnegative), every odd word in the first 2E words is 0.
// If int32, odd words are E random node ids -> OR != 0 with certainty.
__global__ void detect_kernel(const unsigned* __restrict__ w) {
    unsigned local = 0;
    for (int i = blockIdx.x * blockDim.x + threadIdx.x; i < EE;
         i += gridDim.x * blockDim.x)
        local |= w[2 * i + 1];
    #pragma unroll
    for (int off = 16; off; off >>= 1)
        local |= __shfl_xor_sync(0xffffffffu, local, off);
    if ((threadIdx.x & 31) == 0 && local) atomicOr(&g_is32, 1u);
}

__global__ void convert_count_kernel(const void* __restrict__ ei) {
    int e = blockIdx.x * blockDim.x + threadIdx.x;
    if (e >= EE) return;
    int s, d;
    if (g_is32) {
        const int* p = (const int*)ei;
        s = p[e]; d = p[EE + e];
    } else {
        const long long* p = (const long long*)ei;
        s = (int)p[e]; d = (int)p[EE + e];
    }
    g_srcA[e] = s; g_dstA[e] = d;
    atomicAdd(&g_cnt[d], 1);
}

__global__ void dinv_kernel() {
    int i = blockIdx.x * blockDim.x + threadIdx.x;
    if (i < NN) g_dinv[i] = rsqrtf((float)g_cnt[i] + 1.0f);
}

// Single-block exclusive scan of g_cnt -> g_rowptr (N=50000)
__global__ void scan_kernel() {
    __shared__ int s[1024];
    const int T = 1024;
    int tid = threadIdx.x;
    int chunk = (NN + T - 1) / T;
    int beg = tid * chunk;
    int end = min(beg + chunk, NN);
    int sum = 0;
    for (int i = beg; i < end; i++) sum += g_cnt[i];
    s[tid] = sum;
    __syncthreads();
    for (int off = 1; off < T; off <<= 1) {
        int v = (tid >= off) ? s[tid - off] : 0;
        __syncthreads();
        s[tid] += v;
        __syncthreads();
    }
    int run = (tid > 0) ? s[tid - 1] : 0;
    for (int i = beg; i < end; i++) { g_rowptr[i] = run; run += g_cnt[i]; }
    if (tid == T - 1) g_rowptr[NN] = run;
}

__global__ void fill_kernel() {
    int e = blockIdx.x * blockDim.x + threadIdx.x;
    if (e >= EE) return;
    int d = g_dstA[e], s = g_srcA[e];
    int pos = g_rowptr[d] + atomicAdd(&g_fill[d], 1);
    g_col[pos]  = s;
    g_coef[pos] = g_dinv[s] * g_dinv[d];
}

// ---------------- aggregation: T[i,:] = sum_e coef_e * X[src_e,:] + dinv_i^2 * X[i,:] ----------------
template <int W4>  // W4 = width/4 (float4 lanes), blockDim.x == W4
__global__ void agg_kernel(const float* __restrict__ X, float* __restrict__ T) {
    int node = blockIdx.x;
    int t = threadIdx.x;
    const float4* Xv = (const float4*)X;
    float di = g_dinv[node];
    float c0 = di * di;
    float4 self = Xv[(size_t)node * W4 + t];
    float4 acc = make_float4(self.x * c0, self.y * c0, self.z * c0, self.w * c0);
    int beg = g_rowptr[node], end = g_rowptr[node + 1];
    for (int e = beg; e < end; e++) {
        int s = g_col[e];
        float cf = g_coef[e];
        float4 v = Xv[(size_t)s * W4 + t];
        acc.x += cf * v.x; acc.y += cf * v.y;
        acc.z += cf * v.z; acc.w += cf * v.w;
    }
    ((float4*)T)[(size_t)node * W4 + t] = acc;
}

// ---------------- packed fp32x2 helpers ----------------
__device__ __forceinline__ unsigned long long dup2(float a) {
    unsigned long long r;
    asm("mov.b64 %0, {%1, %1};" : "=l"(r) : "f"(a));
    return r;
}
__device__ __forceinline__ unsigned long long fma2(unsigned long long a,
                                                   unsigned long long b,
                                                   unsigned long long c) {
    unsigned long long d;
    asm("fma.rn.f32x2 %0, %1, %2, %3;" : "=l"(d) : "l"(a), "l"(b), "l"(c));
    return d;
}
__device__ __forceinline__ float2 unpack2(unsigned long long v) {
    float2 r;
    asm("mov.b64 {%0, %1}, %2;" : "=f"(r.x), "=f"(r.y) : "l"(v));
    return r;
}

// ---------------- GEMM: C[M,Nc] = relu?(A[M,K] @ W[K,Nc] + bias) ----------------
// 128x128 tile, BK=16, 256 threads, 8x8 per thread (2x2 of 4x4), f32x2 FMA.
template <bool RELU>
__global__ void __launch_bounds__(256, 2) gemm_kernel(
    const float* __restrict__ A, const float* __restrict__ W,
    const float* __restrict__ bias, float* __restrict__ Cv,
    int M, int K, int Nc) {
    __shared__ __align__(16) float As[2][16 * 132];
    __shared__ __align__(16) float Bs[2][16 * 128];
    const int tid = threadIdx.x;
    const int tx = tid & 15, ty = tid >> 4;
    const int mBase = blockIdx.x * 128, nBase = blockIdx.y * 128;

    // A staging: lin = tid*2 + i ; row = tid>>1 ; kq = (tid&1)*2 + i
    const int aRow = tid >> 1;
    const int aKq = (tid & 1) * 2;
    const bool aValid = (mBase + aRow) < M;
    const float* Aptr = A + (size_t)(mBase + aRow) * K + aKq * 4;
    // B staging: brow = ty ; col = tx*8 + i*4
    const float* Wptr = W + (size_t)ty * Nc + nBase + tx * 8;

    unsigned long long c2[8][4];
    #pragma unroll
    for (int i = 0; i < 8; i++)
        #pragma unroll
        for (int j = 0; j < 4; j++) c2[i][j] = 0ull;

    const int nT = K >> 4;
    const float4 z4 = make_float4(0.f, 0.f, 0.f, 0.f);
    float4 ra0, ra1, rb0, rb1;

    // prologue: tile 0 -> smem buf 0
    ra0 = aValid ? *(const float4*)(Aptr)     : z4;
    ra1 = aValid ? *(const float4*)(Aptr + 4) : z4;
    rb0 = *(const float4*)(Wptr);
    rb1 = *(const float4*)(Wptr + 4);
    {
        float* as = As[0]; float* bs = Bs[0];
        as[(aKq * 4 + 0) * 132 + aRow] = ra0.x;
        as[(aKq * 4 + 1) * 132 + aRow] = ra0.y;
        as[(aKq * 4 + 2) * 132 + aRow] = ra0.z;
        as[(aKq * 4 + 3) * 132 + aRow] = ra0.w;
        as[((aKq + 1) * 4 + 0) * 132 + aRow] = ra1.x;
        as[((aKq + 1) * 4 + 1) * 132 + aRow] = ra1.y;
        as[((aKq + 1) * 4 + 2) * 132 + aRow] = ra1.z;
        as[((aKq + 1) * 4 + 3) * 132 + aRow] = ra1.w;
        *(float4*)&bs[ty * 128 + tx * 8]     = rb0;
        *(float4*)&bs[ty * 128 + tx * 8 + 4] = rb1;
    }
    __syncthreads();

    int buf = 0;
    for (int t = 0; t < nT; t++) {
        if (t + 1 < nT) {
            const float* ap = Aptr + (t + 1) * 16;
            ra0 = aValid ? *(const float4*)(ap)     : z4;
            ra1 = aValid ? *(const float4*)(ap + 4) : z4;
            const float* wp = Wptr + (size_t)(t + 1) * 16 * Nc;
            rb0 = *(const float4*)(wp);
            rb1 = *(const float4*)(wp + 4);
        }
        const float* as = As[buf];
        const float* bs = Bs[buf];
        #pragma unroll
        for (int kk = 0; kk < 16; kk++) {
            float4 a0 = *(const float4*)&as[kk * 132 + ty * 4];
            float4 a1 = *(const float4*)&as[kk * 132 + 64 + ty * 4];
            ulonglong2 bb0 = *(const ulonglong2*)&bs[kk * 128 + tx * 4];
            ulonglong2 bb1 = *(const ulonglong2*)&bs[kk * 128 + 64 + tx * 4];
            unsigned long long bq0 = bb0.x, bq1 = bb0.y, bq2 = bb1.x, bq3 = bb1.y;
            float av[8] = {a0.x, a0.y, a0.z, a0.w, a1.x, a1.y, a1.z, a1.w};
            #pragma unroll
            for (int i = 0; i < 8; i++) {
                unsigned long long ad = dup2(av[i]);
                c2[i][0] = fma2(ad, bq0, c2[i][0]);
                c2[i][1] = fma2(ad, bq1, c2[i][1]);
                c2[i][2] = fma2(ad, bq2, c2[i][2]);
                c2[i][3] = fma2(ad, bq3, c2[i][3]);
            }
        }
        if (t + 1 < nT) {
            float* as2 = (float*)As[buf ^ 1];
            float* bs2 = (float*)Bs[buf ^ 1];
            as2[(aKq * 4 + 0) * 132 + aRow] = ra0.x;
            as2[(aKq * 4 + 1) * 132 + aRow] = ra0.y;
            as2[(aKq * 4 + 2) * 132 + aRow] = ra0.z;
            as2[(aKq * 4 + 3) * 132 + aRow] = ra0.w;
            as2[((aKq + 1) * 4 + 0) * 132 + aRow] = ra1.x;
            as2[((aKq + 1) * 4 + 1) * 132 + aRow] = ra1.y;
            as2[((aKq + 1) * 4 + 2) * 132 + aRow] = ra1.z;
            as2[((aKq + 1) * 4 + 3) * 132 + aRow] = ra1.w;
            *(float4*)&bs2[ty * 128 + tx * 8]     = rb0;
            *(float4*)&bs2[ty * 128 + tx * 8 + 4] = rb1;
            __syncthreads();
            buf ^= 1;
        }
    }

    // epilogue
    float4 bias0 = *(const float4*)&bias[nBase + tx * 4];
    float4 bias1 = *(const float4*)&bias[nBase + 64 + tx * 4];
    #pragma unroll
    for (int ih = 0; ih < 2; ih++) {
        #pragma unroll
        for (int r = 0; r < 4; r++) {
            int i = ih * 4 + r;
            int gr = mBase + ih * 64 + ty * 4 + r;
            if (gr < M) {
                float2 p0 = unpack2(c2[i][0]), p1 = unpack2(c2[i][1]);
                float2 p2 = unpack2(c2[i][2]), p3 = unpack2(c2[i][3]);
                float4 v0 = make_float4(p0.x + bias0.x, p0.y + bias0.y,
                                        p1.x + bias0.z, p1.y + bias0.w);
                float4 v1 = make_float4(p2.x + bias1.x, p2.y + bias1.y,
                                        p3.x + bias1.z, p3.y + bias1.w);
                if (RELU) {
                    v0.x = fmaxf(v0.x, 0.f); v0.y = fmaxf(v0.y, 0.f);
                    v0.z = fmaxf(v0.z, 0.f); v0.w = fmaxf(v0.w, 0.f);
                    v1.x = fmaxf(v1.x, 0.f); v1.y = fmaxf(v1.y, 0.f);
                    v1.z = fmaxf(v1.z, 0.f); v1.w = fmaxf(v1.w, 0.f);
                }
                *(float4*)&Cv[(size_t)gr * Nc + nBase + tx * 4]      = v0;
                *(float4*)&Cv[(size_t)gr * Nc + nBase + 64 + tx * 4] = v1;
            }
        }
    }
}

// ---------------- final small GEMM: S[N,3] = X[N,512] @ W1[512,3] ----------------
__global__ void gemm_small_kernel(const float* __restrict__ X,
                                  const float* __restrict__ W1,
                                  float* __restrict__ S) {
    int row = blockIdx.x * (blockDim.x / 32) + (threadIdx.x >> 5);
    int lane = threadIdx.x & 31;
    if (row >= NN) return;
    float a0 = 0.f, a1 = 0.f, a2 = 0.f;
    const float* xr = X + (size_t)row * HH;
    for (int k = lane; k < HH; k += 32) {
        float xv = xr[k];
        a0 += xv * W1[k * 3 + 0];
        a1 += xv * W1[k * 3 + 1];
        a2 += xv * W1[k * 3 + 2];
    }
    #pragma unroll
    for (int off = 16; off; off >>= 1) {
        a0 += __shfl_down_sync(0xffffffffu, a0, off);
        a1 += __shfl_down_sync(0xffffffffu, a1, off);
        a2 += __shfl_down_sync(0xffffffffu, a2, off);
    }
    if (lane == 0) {
        S[row * 3 + 0] = a0;
        S[row * 3 + 1] = a1;
        S[row * 3 + 2] = a2;
    }
}

// ---------------- final aggregation on 3 cols + bias ----------------
__global__ void agg_final_kernel(const float* __restrict__ S,
                                 const float* __restrict__ b1,
                                 float* __restrict__ out) {
    int i = blockIdx.x * blockDim.x + threadIdx.x;
    if (i >= NN) return;
    float di = g_dinv[i];
    float c0 = di * di;
    float a0 = c0 * S[i * 3 + 0];
    float a1 = c0 * S[i * 3 + 1];
    float a2 = c0 * S[i * 3 + 2];
    int beg = g_rowptr[i], end = g_rowptr[i + 1];
    for (int e = beg; e < end; e++) {
        int s = g_col[e];
        float cf = g_coef[e];
        a0 += cf * S[s * 3 + 0];
        a1 += cf * S[s * 3 + 1];
        a2 += cf * S[s * 3 + 2];
    }
    out[i * 3 + 0] = a0 + b1[0];
    out[i * 3 + 1] = a1 + b1[1];
    out[i * 3 + 2] = a2 + b1[2];
}

// ---------------- host orchestration ----------------
extern "C" void kernel_launch(void* const* d_in, const int* in_sizes, int n_in,
                              void* d_out, int out_size) {
    const float* x  = (const float*)d_in[0];
    const void*  ei = d_in[1];
    const float* W0 = (const float*)d_in[2];
    const float* b0 = (const float*)d_in[3];
    const float* Wr = (const float*)d_in[4];
    const float* br = (const float*)d_in[5];
    const float* W1 = (const float*)d_in[6];
    const float* b1 = (const float*)d_in[7];
    float* out  = (float*)d_out;
    float* outX = out + (size_t)NN * CC;  // second tuple element: x [N,512]

    float *gX, *gT, *gS;
    cudaGetSymbolAddress((void**)&gX, g_X);
    cudaGetSymbolAddress((void**)&gT, g_T);
    cudaGetSymbolAddress((void**)&gS, g_S);

    // CSR + normalization preprocessing (per call; deterministic given inputs)
    zero_kernel<<<(NN + 255) / 256, 256>>>();
    detect_kernel<<<256, 256>>>((const unsigned*)ei);
    convert_count_kernel<<<(EE + 255) / 256, 256>>>(ei);
    dinv_kernel<<<(NN + 255) / 256, 256>>>();
    scan_kernel<<<1, 1024>>>();
    fill_kernel<<<(EE + 255) / 256, 256>>>();

    dim3 gg((NN + 127) / 128, HH / 128);
    dim3 gb(256);

    // layer 0: aggregate on F=256 first, then GEMM(K=256)+bias+relu
    agg_kernel<FF / 4><<<NN, FF / 4>>>(x, gT);
    gemm_kernel<true><<<gg, gb>>>(gT, W0, b0, gX, NN, FF, HH);

    // 12 residual-block convs: all relu(A x W + b)
    for (int L = 0; L < 12; L++) {
        agg_kernel<HH / 4><<<NN, HH / 4>>>(gX, gT);
        float* dst = (L == 11) ? outX : gX;
        gemm_kernel<true><<<gg, gb>>>(gT, Wr + (size_t)L * HH * HH,
                                      br + (size_t)L * HH, dst, NN, HH, HH);
    }

    // final conv: GEMM first (H->3), then aggregate on 3 cols + bias
    gemm_small_kernel<<<(NN + 7) / 8, 256>>>(outX, W1, gS);
    agg_final_kernel<<<(NN + 255) / 256, 256>>>(gS, b1, out);
}

// round 3
// speedup vs baseline: 1.8428x; 1.8428x over previous
#include <cuda_runtime.h>
#include <cuda_bf16.h>
#include <cstdint>

#define NN 50000
#define EE 400000
#define FF 256
#define HH 512
#define CC 3
#define NPAD 50048              // 391 * 128

// ---------------- device scratch ----------------
__device__ float g_X[(size_t)NPAD * HH];          // fp32 activations
__device__ __nv_bfloat16 g_Ah[(size_t)NPAD * HH]; // agg output hi
__device__ __nv_bfloat16 g_Am[(size_t)NPAD * HH]; // agg output mid
__device__ __nv_bfloat16 g_Wh[(size_t)13 * HH * HH];  // transposed [n][k]
__device__ __nv_bfloat16 g_Wm[(size_t)13 * HH * HH];
__device__ float g_S[(size_t)NN * CC];
__device__ float g_dinv[NN];
__device__ float g_coef[EE];
__device__ int   g_srcA[EE];
__device__ int   g_dstA[EE];
__device__ int   g_col[EE];
__device__ int   g_cnt[NN];
__device__ int   g_fill[NN];
__device__ int   g_rowptr[NN + 1];
__device__ unsigned g_is32;

// ---------------- preprocessing ----------------
__global__ void zero_kernel() {
    int i = blockIdx.x * blockDim.x + threadIdx.x;
    if (i < NN) { g_cnt[i] = 0; g_fill[i] = 0; }
    if (i == 0) g_is32 = 0u;
}

__global__ void detect_kernel(const unsigned* __restrict__ w) {
    unsigned local = 0;
    for (int i = blockIdx.x * blockDim.x + threadIdx.x; i < EE;
         i += gridDim.x * blockDim.x)
        local |= w[2 * i + 1];
    #pragma unroll
    for (int off = 16; off; off >>= 1)
        local |= __shfl_xor_sync(0xffffffffu, local, off);
    if ((threadIdx.x & 31) == 0 && local) atomicOr(&g_is32, 1u);
}

__global__ void convert_count_kernel(const void* __restrict__ ei) {
    int e = blockIdx.x * blockDim.x + threadIdx.x;
    if (e >= EE) return;
    int s, d;
    if (g_is32) {
        const int* p = (const int*)ei;
        s = p[e]; d = p[EE + e];
    } else {
        const long long* p = (const long long*)ei;
        s = (int)p[e]; d = (int)p[EE + e];
    }
    g_srcA[e] = s; g_dstA[e] = d;
    atomicAdd(&g_cnt[d], 1);
}

__global__ void dinv_kernel() {
    int i = blockIdx.x * blockDim.x + threadIdx.x;
    if (i < NN) g_dinv[i] = rsqrtf((float)g_cnt[i] + 1.0f);
}

__global__ void scan_kernel() {
    __shared__ int s[1024];
    const int T = 1024;
    int tid = threadIdx.x;
    int chunk = (NN + T - 1) / T;
    int beg = tid * chunk;
    int end = min(beg + chunk, NN);
    int sum = 0;
    for (int i = beg; i < end; i++) sum += g_cnt[i];
    s[tid] = sum;
    __syncthreads();
    for (int off = 1; off < T; off <<= 1) {
        int v = (tid >= off) ? s[tid - off] : 0;
        __syncthreads();
        s[tid] += v;
        __syncthreads();
    }
    int run = (tid > 0) ? s[tid - 1] : 0;
    for (int i = beg; i < end; i++) { g_rowptr[i] = run; run += g_cnt[i]; }
    if (tid == T - 1) g_rowptr[NN] = run;
}

__global__ void fill_kernel() {
    int e = blockIdx.x * blockDim.x + threadIdx.x;
    if (e >= EE) return;
    int d = g_dstA[e], s = g_srcA[e];
    int pos = g_rowptr[d] + atomicAdd(&g_fill[d], 1);
    g_col[pos]  = s;
    g_coef[pos] = g_dinv[s] * g_dinv[d];
}

// ---------------- weight transpose + bf16 hi/mid split ----------------
__global__ void wsplit_kernel(const float* __restrict__ W0,
                              const float* __restrict__ Wr) {
    int L = blockIdx.y;
    int n = blockIdx.x;
    int K = (L == 0) ? FF : HH;
    const float* W = (L == 0) ? W0 : (Wr + (size_t)(L - 1) * HH * HH);
    size_t slot = (size_t)L * HH * HH;
    for (int k = threadIdx.x; k < K; k += blockDim.x) {
        float x = W[(size_t)k * HH + n];
        __nv_bfloat16 h = __float2bfloat16_rn(x);
        float r = x - __bfloat162float(h);
        g_Wh[slot + (size_t)n * K + k] = h;
        g_Wm[slot + (size_t)n * K + k] = __float2bfloat16_rn(r);
    }
}

// ---------------- aggregation: bf16 hi/mid split output ----------------
template <int W4>
__global__ void agg_kernel(const float* __restrict__ X,
                           __nv_bfloat16* __restrict__ Th,
                           __nv_bfloat16* __restrict__ Tm, int sA) {
    int node = blockIdx.x;
    int t = threadIdx.x;
    const float4* Xv = (const float4*)X;
    float di = g_dinv[node];
    float c0 = di * di;
    float4 self = Xv[(size_t)node * W4 + t];
    float4 acc = make_float4(self.x * c0, self.y * c0, self.z * c0, self.w * c0);
    int beg = g_rowptr[node], end = g_rowptr[node + 1];
    for (int e = beg; e < end; e++) {
        int s = g_col[e];
        float cf = g_coef[e];
        float4 v = Xv[(size_t)s * W4 + t];
        acc.x += cf * v.x; acc.y += cf * v.y;
        acc.z += cf * v.z; acc.w += cf * v.w;
    }
    float vals[4] = {acc.x, acc.y, acc.z, acc.w};
    unsigned hb[4], mb[4];
    #pragma unroll
    for (int i = 0; i < 4; i++) {
        __nv_bfloat16 h = __float2bfloat16_rn(vals[i]);
        float r = vals[i] - __bfloat162float(h);
        __nv_bfloat16 m = __float2bfloat16_rn(r);
        hb[i] = (unsigned)__bfloat16_as_ushort(h);
        mb[i] = (unsigned)__bfloat16_as_ushort(m);
    }
    uint2 ph, pm;
    ph.x = hb[0] | (hb[1] << 16); ph.y = hb[2] | (hb[3] << 16);
    pm.x = mb[0] | (mb[1] << 16); pm.y = mb[2] | (mb[3] << 16);
    size_t off = (size_t)node * sA + 4 * t;
    *(uint2*)(Th + off) = ph;
    *(uint2*)(Tm + off) = pm;
}

// ---------------- HMMA (mma.sync) bf16x3 GEMM ----------------
// C[M,512] = relu(A[M,K] @ W[K,512] + bias)
// Block 128x128, 8 warps (2M x 4N), warp tile 64x32, BK=32, double-buffered cp.async.
// smem per stage: Ah/Am/Bh/Bm each [128][40] bf16 (pitch 80B, bank-conflict-free frags).
#define APITCH_B 80          // bytes per smem row
#define ARR_B    10240       // bytes per array (128*80)
#define STAGE_B  40960       // 4 arrays
#define GSMEM_B  81920       // 2 stages

#define MMA_B16(cc, A0, A1, A2, A3, B0, B1)                                   \
    asm volatile(                                                             \
        "mma.sync.aligned.m16n8k16.row.col.f32.bf16.bf16.f32 "                \
        "{%0,%1,%2,%3}, {%4,%5,%6,%7}, {%8,%9}, {%0,%1,%2,%3};"               \
        : "+f"(cc[0]), "+f"(cc[1]), "+f"(cc[2]), "+f"(cc[3])                  \
        : "r"(A0), "r"(A1), "r"(A2), "r"(A3), "r"(B0), "r"(B1))

__global__ void __launch_bounds__(256, 2) gemm_mma_kernel(
    const __nv_bfloat16* __restrict__ Ah, const __nv_bfloat16* __restrict__ Am,
    const __nv_bfloat16* __restrict__ Wh, const __nv_bfloat16* __restrict__ Wm,
    const float* __restrict__ bias, float* __restrict__ Xout,
    int M, int K, int sA) {
    extern __shared__ char smb[];
    uint32_t sbase;
    asm("{ .reg .u64 t; cvta.to.shared.u64 t, %1; cvt.u32.u64 %0, t; }"
        : "=r"(sbase) : "l"(smb));

    const int tid = threadIdx.x;
    const int lane = tid & 31, wid = tid >> 5;
    const int g = lane >> 2, t4 = lane & 3;
    const int warpM = wid & 1, warpN = wid >> 1;
    const int mBase = blockIdx.x * 128, nBase = blockIdx.y * 128;

    // staging task: q in [0,512): row=q>>2, c16=q&3 ; thread does q=tid, tid+256
    const int nChunks = K >> 5;

    float acc[4][4][4];
    #pragma unroll
    for (int i = 0; i < 4; i++)
        #pragma unroll
        for (int j = 0; j < 4; j++)
            #pragma unroll
            for (int v = 0; v < 4; v++) acc[i][j][v] = 0.f;

    #define STAGE_LOAD(buf, chunk) do {                                        \
        int k0 = (chunk) * 32;                                                 \
        uint32_t sb = sbase + (buf) * STAGE_B;                                 \
        _Pragma("unroll")                                                      \
        for (int h = 0; h < 2; h++) {                                          \
            int q = tid + h * 256;                                             \
            int row = q >> 2, c16 = q & 3;                                     \
            uint32_t ds = sb + row * APITCH_B + c16 * 16;                      \
            int gr = mBase + row;                                              \
            int vsz = (gr < M) ? 16 : 0;                                       \
            long long aoff = (long long)(gr < M ? gr : 0) * sA + k0 + c16 * 8; \
            asm volatile("cp.async.cg.shared.global [%0], [%1], 16, %2;"       \
                :: "r"(ds), "l"(Ah + aoff), "r"(vsz));                         \
            asm volatile("cp.async.cg.shared.global [%0], [%1], 16, %2;"       \
                :: "r"(ds + ARR_B), "l"(Am + aoff), "r"(vsz));                 \
            long long boff = (long long)(nBase + row) * K + k0 + c16 * 8;     \
            asm volatile("cp.async.cg.shared.global [%0], [%1], 16;"           \
                :: "r"(ds + 2 * ARR_B), "l"(Wh + boff));                       \
            asm volatile("cp.async.cg.shared.global [%0], [%1], 16;"           \
                :: "r"(ds + 3 * ARR_B), "l"(Wm + boff));                       \
        }                                                                      \
        asm volatile("cp.async.commit_group;");                                \
    } while (0)

    STAGE_LOAD(0, 0);

    for (int c = 0; c < nChunks; c++) {
        int b = c & 1;
        if (c + 1 < nChunks) {
            STAGE_LOAD(b ^ 1, c + 1);
            asm volatile("cp.async.wait_group 1;");
        } else {
            asm volatile("cp.async.wait_group 0;");
        }
        __syncthreads();

        const char* bufA = smb + b * STAGE_B;
        const char* bufB = bufA + 2 * ARR_B;
        #pragma unroll
        for (int kk = 0; kk < 32; kk += 16) {
            // B fragments (4 n-tiles x {hi,mid})
            uint32_t bh[4][2], bm[4][2];
            #pragma unroll
            for (int j = 0; j < 4; j++) {
                const char* bp = bufB + (warpN * 32 + j * 8 + g) * APITCH_B +
                                 (kk + 2 * t4) * 2;
                bh[j][0] = *(const uint32_t*)(bp);
                bh[j][1] = *(const uint32_t*)(bp + 16);
                bm[j][0] = *(const uint32_t*)(bp + ARR_B);
                bm[j][1] = *(const uint32_t*)(bp + ARR_B + 16);
            }
            #pragma unroll
            for (int i = 0; i < 4; i++) {
                const char* ap = bufA + (warpM * 64 + i * 16 + g) * APITCH_B +
                                 (kk + 2 * t4) * 2;
                uint32_t ah0 = *(const uint32_t*)(ap);
                uint32_t ah1 = *(const uint32_t*)(ap + 8 * APITCH_B);
                uint32_t ah2 = *(const uint32_t*)(ap + 16);
                uint32_t ah3 = *(const uint32_t*)(ap + 8 * APITCH_B + 16);
                uint32_t am0 = *(const uint32_t*)(ap + ARR_B);
                uint32_t am1 = *(const uint32_t*)(ap + ARR_B + 8 * APITCH_B);
                uint32_t am2 = *(const uint32_t*)(ap + ARR_B + 16);
                uint32_t am3 = *(const uint32_t*)(ap + ARR_B + 8 * APITCH_B + 16);
                #pragma unroll
                for (int j = 0; j < 4; j++) {
                    MMA_B16(acc[i][j], ah0, ah1, ah2, ah3, bh[j][0], bh[j][1]);
                    MMA_B16(acc[i][j], am0, am1, am2, am3, bh[j][0], bh[j][1]);
                    MMA_B16(acc[i][j], ah0, ah1, ah2, ah3, bm[j][0], bm[j][1]);
                }
            }
        }
        __syncthreads();
    }

    // epilogue: bias + relu, fp32 out (row stride HH)
    #pragma unroll
    for (int j = 0; j < 4; j++) {
        int col = nBase + warpN * 32 + j * 8 + 2 * t4;
        float bv0 = __ldg(&bias[col]), bv1 = __ldg(&bias[col + 1]);
        #pragma unroll
        for (int i = 0; i < 4; i++) {
            int r0 = mBase + warpM * 64 + i * 16 + g;
            if (r0 < M) {
                float2 v0 = make_float2(fmaxf(acc[i][j][0] + bv0, 0.f),
                                        fmaxf(acc[i][j][1] + bv1, 0.f));
                *(float2*)(Xout + (size_t)r0 * HH + col) = v0;
            }
            int r1 = r0 + 8;
            if (r1 < M) {
                float2 v1 = make_float2(fmaxf(acc[i][j][2] + bv0, 0.f),
                                        fmaxf(acc[i][j][3] + bv1, 0.f));
                *(float2*)(Xout + (size_t)r1 * HH + col) = v1;
            }
        }
    }
}

// ---------------- final small GEMM: S[N,3] = X[N,512] @ W1[512,3] ----------------
__global__ void gemm_small_kernel(const float* __restrict__ X,
                                  const float* __restrict__ W1,
                                  float* __restrict__ S) {
    int row = blockIdx.x * (blockDim.x / 32) + (threadIdx.x >> 5);
    int lane = threadIdx.x & 31;
    if (row >= NN) return;
    float a0 = 0.f, a1 = 0.f, a2 = 0.f;
    const float* xr = X + (size_t)row * HH;
    for (int k = lane; k < HH; k += 32) {
        float xv = xr[k];
        a0 += xv * W1[k * 3 + 0];
        a1 += xv * W1[k * 3 + 1];
        a2 += xv * W1[k * 3 + 2];
    }
    #pragma unroll
    for (int off = 16; off; off >>= 1) {
        a0 += __shfl_down_sync(0xffffffffu, a0, off);
        a1 += __shfl_down_sync(0xffffffffu, a1, off);
        a2 += __shfl_down_sync(0xffffffffu, a2, off);
    }
    if (lane == 0) {
        S[row * 3 + 0] = a0;
        S[row * 3 + 1] = a1;
        S[row * 3 + 2] = a2;
    }
}

__global__ void agg_final_kernel(const float* __restrict__ S,
                                 const float* __restrict__ b1,
                                 float* __restrict__ out) {
    int i = blockIdx.x * blockDim.x + threadIdx.x;
    if (i >= NN) return;
    float di = g_dinv[i];
    float c0 = di * di;
    float a0 = c0 * S[i * 3 + 0];
    float a1 = c0 * S[i * 3 + 1];
    float a2 = c0 * S[i * 3 + 2];
    int beg = g_rowptr[i], end = g_rowptr[i + 1];
    for (int e = beg; e < end; e++) {
        int s = g_col[e];
        float cf = g_coef[e];
        a0 += cf * S[s * 3 + 0];
        a1 += cf * S[s * 3 + 1];
        a2 += cf * S[s * 3 + 2];
    }
    out[i * 3 + 0] = a0 + b1[0];
    out[i * 3 + 1] = a1 + b1[1];
    out[i * 3 + 2] = a2 + b1[2];
}

// ---------------- host orchestration ----------------
extern "C" void kernel_launch(void* const* d_in, const int* in_sizes, int n_in,
                              void* d_out, int out_size) {
    const float* x  = (const float*)d_in[0];
    const void*  ei = d_in[1];
    const float* W0 = (const float*)d_in[2];
    const float* b0 = (const float*)d_in[3];
    const float* Wr = (const float*)d_in[4];
    const float* br = (const float*)d_in[5];
    const float* W1 = (const float*)d_in[6];
    const float* b1 = (const float*)d_in[7];
    float* out  = (float*)d_out;
    float* outX = out + (size_t)NN * CC;

    float *gX, *gS;
    __nv_bfloat16 *gAh, *gAm, *gWh, *gWm;
    cudaGetSymbolAddress((void**)&gX,  g_X);
    cudaGetSymbolAddress((void**)&gS,  g_S);
    cudaGetSymbolAddress((void**)&gAh, g_Ah);
    cudaGetSymbolAddress((void**)&gAm, g_Am);
    cudaGetSymbolAddress((void**)&gWh, g_Wh);
    cudaGetSymbolAddress((void**)&gWm, g_Wm);

    cudaFuncSetAttribute(gemm_mma_kernel,
                         cudaFuncAttributeMaxDynamicSharedMemorySize, GSMEM_B);

    // preprocessing: CSR + normalization + weight split
    zero_kernel<<<(NN + 255) / 256, 256>>>();
    detect_kernel<<<256, 256>>>((const unsigned*)ei);
    convert_count_kernel<<<(EE + 255) / 256, 256>>>(ei);
    dinv_kernel<<<(NN + 255) / 256, 256>>>();
    scan_kernel<<<1, 1024>>>();
    fill_kernel<<<(EE + 255) / 256, 256>>>();
    wsplit_kernel<<<dim3(HH, 13), 256>>>(W0, Wr);

    dim3 gg(NPAD / 128, 4);

    // layer 0: agg on F=256 (split output), then HMMA GEMM K=256
    agg_kernel<FF / 4><<<NN, FF / 4>>>(x, gAh, gAm, FF);
    gemm_mma_kernel<<<gg, 256, GSMEM_B>>>(gAh, gAm, gWh, gWm, b0, gX,
                                          NN, FF, FF);

    // 12 residual-block convs: relu(A x W + b)
    for (int L = 1; L <= 12; L++) {
        agg_kernel<HH / 4><<<NN, HH / 4>>>(gX, gAh, gAm, HH);
        float* dst = (L == 12) ? outX : gX;
        gemm_mma_kernel<<<gg, 256, GSMEM_B>>>(
            gAh, gAm,
            gWh + (size_t)L * HH * HH, gWm + (size_t)L * HH * HH,
            br + (size_t)(L - 1) * HH, dst, NN, HH, HH);
    }

    // final conv: GEMM first (H->3), then aggregate on 3 cols + bias
    gemm_small_kernel<<<(NN + 7) / 8, 256>>>(outX, W1, gS);
    agg_final_kernel<<<(NN + 255) / 256, 256>>>(gS, b1, out);
}